// round 9
// baseline (speedup 1.0000x reference)
#include <cuda_runtime.h>
#include <cuda_bf16.h>
#include <cstdint>

// SplitMLP via mma.sync bf16 (hi/lo split, 3 cross-products ~ fp32 accuracy).
// 256-thread CTAs (8 warps x 16 rows), NG groups per CTA, register prefetch
// of group g+1 overlapping group g's MMA.

constexpr int B = 128;
constexpr int C = 16;
constexpr int V = 32;
constexpr int H = 64;
constexpr int O = 4;
constexpr int KTOT = 48;
constexpr int PX = 104;              // bf16 pitch: 48 hi + 48 lo + 8 pad (208 B)
constexpr int PXB = PX * 2;
constexpr int NG = 10;               // groups per CTA
constexpr int NT = 256;              // threads

typedef uint32_t u32;

// ---------- helpers ----------
__device__ __forceinline__ u32 smem_u32(const void* p) {
    u32 a;
    asm("{ .reg .u64 t; cvta.to.shared.u64 t, %1; cvt.u32.u64 %0, t; }"
        : "=r"(a) : "l"(p));
    return a;
}
__device__ __forceinline__ u32 cvt2bf16(float lo, float hi) {
    u32 d;
    asm("cvt.rn.bf16x2.f32 %0, %1, %2;" : "=r"(d) : "f"(hi), "f"(lo));
    return d;
}
__device__ __forceinline__ void ldsm4(u32* r, u32 addr) {
    asm volatile("ldmatrix.sync.aligned.m8n8.x4.shared.b16 {%0,%1,%2,%3}, [%4];"
                 : "=r"(r[0]), "=r"(r[1]), "=r"(r[2]), "=r"(r[3]) : "r"(addr));
}
__device__ __forceinline__ void mma_bf16(float* c, const u32* a, const u32* b) {
    asm volatile(
        "mma.sync.aligned.m16n8k16.row.col.f32.bf16.bf16.f32 "
        "{%0,%1,%2,%3}, {%4,%5,%6,%7}, {%8,%9}, {%0,%1,%2,%3};"
        : "+f"(c[0]), "+f"(c[1]), "+f"(c[2]), "+f"(c[3])
        : "r"(a[0]), "r"(a[1]), "r"(a[2]), "r"(a[3]), "r"(b[0]), "r"(b[1]));
}

// Convert float4 -> bf16 hi/lo pairs and store at (row, col) + (row, col+48).
__device__ __forceinline__ void cvt_store4(__nv_bfloat16* base, int row, int col,
                                           float4 v) {
    u32 h01 = cvt2bf16(v.x, v.y);
    u32 h23 = cvt2bf16(v.z, v.w);
    float l0 = v.x - __uint_as_float(h01 << 16);
    float l1 = v.y - __uint_as_float(h01 & 0xffff0000u);
    float l2 = v.z - __uint_as_float(h23 << 16);
    float l3 = v.w - __uint_as_float(h23 & 0xffff0000u);
    u32 lo01 = cvt2bf16(l0, l1);
    u32 lo23 = cvt2bf16(l2, l3);
    *reinterpret_cast<uint2*>(base + row * PX + col) = make_uint2(h01, h23);
    *reinterpret_cast<uint2*>(base + row * PX + col + KTOT) = make_uint2(lo01, lo23);
}

struct GroupRegs {
    float4 it[4];   // items slice (4 float4 per thread @256 threads)
    float4 wd;      // W1_day (1 float4)
    float4 wv[2];   // W1_var (2 float4)
    float  w2;      // W2 (1 float per thread)
    float  b1v;     // t<64
    float  b2v;     // t<4
};

__device__ __forceinline__ void load_group(
    GroupRegs& r, int g, int t, int G,
    const float4* itF4, const float4* wdF4, const float4* wvF4,
    const float* w2p, const float* b1p, const float* b2p)
{
    const size_t rowBase = (size_t)(t >> 3) * G;   // items row (t>>3) + j*32
#pragma unroll
    for (int j = 0; j < 4; ++j)
        r.it[j] = itF4[((rowBase + (size_t)j * 32 * G) + g) * 8 + (t & 7)];
    r.wd = wdF4[(size_t)g * 256 + t];
#pragma unroll
    for (int j = 0; j < 2; ++j)
        r.wv[j] = wvF4[(size_t)g * 512 + t + j * 256];
    r.w2 = w2p[(size_t)g * 256 + t];
    if (t < 64) r.b1v = b1p[(size_t)g * 64 + t];
    if (t < 4)  r.b2v = b2p[(size_t)g * 4 + t];
}

__global__ __launch_bounds__(NT, 2) void splitmlp_mma(
    const float* __restrict__ day,     // (B, C)
    const float* __restrict__ items,   // (B, G, V)
    const float* __restrict__ W1_day,  // (G, H, C)
    const float* __restrict__ W1_var,  // (G, H, V)
    const float* __restrict__ b1,      // (G, H)
    const float* __restrict__ W2,      // (G, O, H)
    const float* __restrict__ b2,      // (G, O)
    float* __restrict__ out,           // (B, G, O)
    int G)
{
    __shared__ __nv_bfloat16 sX[B * PX];    // 26624 B
    __shared__ __nv_bfloat16 sW1[H * PX];   // 13312 B
    __shared__ float sW2[O * H];            // [o][h]
    __shared__ float sB1[H];
    __shared__ float sB2[O];

    const int t = threadIdx.x;
    const int wid = t >> 5;
    const int lane = t & 31;
    const int g0 = blockIdx.x * NG;
    const int gEnd = (g0 + NG < G) ? (g0 + NG) : G;
    if (g0 >= G) return;

    const float4* itF4 = reinterpret_cast<const float4*>(items);
    const float4* wdF4 = reinterpret_cast<const float4*>(W1_day);
    const float4* wvF4 = reinterpret_cast<const float4*>(W1_var);

    GroupRegs cur;
    load_group(cur, g0, t, G, itF4, wdF4, wvF4, W2, b1, b2);

    // day staged once per CTA: X rows, k 0..15 (+lo plane)
    {
        const float4* p = reinterpret_cast<const float4*>(day);
#pragma unroll
        for (int j = 0; j < 2; ++j) {
            int f = t + j * NT;
            cvt_store4(sX, f >> 2, (f & 3) * 4, p[f]);
        }
    }

    // ---- per-lane ldmatrix addresses (group-invariant) ----
    const u32 sbX = smem_u32(sX);
    const u32 sbW = smem_u32(sW1);
    const int r8 = lane & 7, sel = lane >> 3;
    const int wbase = wid * 16;     // 16 M-rows per warp
    // A: m0=rows0-7 klo, m1=rows8-15 klo, m2=rows0-7 khi, m3=rows8-15 khi
    const u32 aAddr = sbX + (u32)((wbase + ((sel & 1) << 3) + r8) * PXB +
                                  ((sel & 2) ? 16 : 0));
    // B: m0=n0-7 klo, m1=n0-7 khi, m2=n8-15 klo, m3=n8-15 khi
    const u32 bAddr = sbW + (u32)(((((sel >> 1) & 1) << 3) + r8) * PXB +
                                  ((sel & 1) << 4));
    constexpr int NT_STRIDE = 16 * PXB;
    constexpr int LO_OFF = KTOT * 2;
    const int q = lane & 3;

#pragma unroll 1
    for (int g = g0; g < gEnd; ++g) {
        // ---- stage current group from registers ----
#pragma unroll
        for (int j = 0; j < 4; ++j)
            cvt_store4(sX, (t >> 3) + j * 32, 16 + (t & 7) * 4, cur.it[j]);
        cvt_store4(sW1, t >> 2, (t & 3) * 4, cur.wd);
#pragma unroll
        for (int j = 0; j < 2; ++j)
            cvt_store4(sW1, (t >> 3) + j * 32, 16 + (t & 7) * 4, cur.wv[j]);
        sW2[t] = cur.w2;
        if (t < 64) sB1[t] = cur.b1v;
        if (t < 4)  sB2[t] = cur.b2v;
        __syncthreads();

        // ---- prefetch next group (overlaps with MMA below) ----
        GroupRegs nxt;
        const bool more = (g + 1 < gEnd);
        if (more)
            load_group(nxt, g + 1, t, G, itF4, wdF4, wvF4, W2, b1, b2);

        // ---- fc1 MMA: 3 k-chunks x 3 hi/lo passes ----
        float acc[8][4];
#pragma unroll
        for (int nt = 0; nt < 8; ++nt)
#pragma unroll
            for (int i = 0; i < 4; ++i) acc[nt][i] = 0.0f;

#pragma unroll
        for (int kk = 0; kk < 3; ++kk) {
            const int kOff = kk * 32;
            u32 ah[4], bh[4][4];
            ldsm4(ah, aAddr + kOff);
#pragma unroll
            for (int np = 0; np < 4; ++np)
                ldsm4(bh[np], bAddr + np * NT_STRIDE + kOff);
            // Ah * Bh
#pragma unroll
            for (int np = 0; np < 4; ++np) {
                mma_bf16(acc[2 * np + 0], ah, &bh[np][0]);
                mma_bf16(acc[2 * np + 1], ah, &bh[np][2]);
            }
            // Ah * Bl
#pragma unroll
            for (int np = 0; np < 4; ++np) {
                u32 bl[4];
                ldsm4(bl, bAddr + np * NT_STRIDE + LO_OFF + kOff);
                mma_bf16(acc[2 * np + 0], ah, &bl[0]);
                mma_bf16(acc[2 * np + 1], ah, &bl[2]);
            }
            // Al * Bh
            {
                u32 al[4];
                ldsm4(al, aAddr + LO_OFF + kOff);
#pragma unroll
                for (int np = 0; np < 4; ++np) {
                    mma_bf16(acc[2 * np + 0], al, &bh[np][0]);
                    mma_bf16(acc[2 * np + 1], al, &bh[np][2]);
                }
            }
        }

        // ---- epilogue: relu(h + b1), fc2, quad reduction ----
        float y[2][4];
#pragma unroll
        for (int rp = 0; rp < 2; ++rp)
#pragma unroll
            for (int o = 0; o < O; ++o) y[rp][o] = 0.0f;

#pragma unroll
        for (int nt = 0; nt < 8; ++nt) {
            const int h0 = nt * 8 + q * 2;
            const float2 bb = *reinterpret_cast<const float2*>(&sB1[h0]);
            float v00 = fmaxf(acc[nt][0] + bb.x, 0.0f);
            float v01 = fmaxf(acc[nt][1] + bb.y, 0.0f);
            float v10 = fmaxf(acc[nt][2] + bb.x, 0.0f);
            float v11 = fmaxf(acc[nt][3] + bb.y, 0.0f);
#pragma unroll
            for (int o = 0; o < O; ++o) {
                const float2 w = *reinterpret_cast<const float2*>(&sW2[o * H + h0]);
                y[0][o] = fmaf(v00, w.x, fmaf(v01, w.y, y[0][o]));
                y[1][o] = fmaf(v10, w.x, fmaf(v11, w.y, y[1][o]));
            }
        }
#pragma unroll
        for (int d = 1; d < 4; d <<= 1) {
#pragma unroll
            for (int rp = 0; rp < 2; ++rp)
#pragma unroll
                for (int o = 0; o < O; ++o)
                    y[rp][o] += __shfl_xor_sync(0xffffffffu, y[rp][o], d);
        }

        if (q == 0) {
            const int rbase = wbase + (lane >> 2);
#pragma unroll
            for (int rp = 0; rp < 2; ++rp) {
                const int row = rbase + rp * 8;
                float4 res = make_float4(y[rp][0] + sB2[0],
                                         y[rp][1] + sB2[1],
                                         y[rp][2] + sB2[2],
                                         y[rp][3] + sB2[3]);
                *reinterpret_cast<float4*>(out + ((size_t)row * G + g) * O) = res;
            }
        }

        __syncthreads();   // smem reusable for next group's staging
        if (more) cur = nxt;
    }
}

extern "C" void kernel_launch(void* const* d_in, const int* in_sizes, int n_in,
                              void* d_out, int out_size) {
    const float* day    = (const float*)d_in[0];
    const float* items  = (const float*)d_in[1];
    const float* W1_day = (const float*)d_in[2];
    const float* W1_var = (const float*)d_in[3];
    const float* b1     = (const float*)d_in[4];
    const float* W2     = (const float*)d_in[5];
    const float* b2     = (const float*)d_in[6];
    float* out = (float*)d_out;

    const int G = in_sizes[1] / (B * V);   // items = B*G*V
    const int grid = (G + NG - 1) / NG;

    splitmlp_mma<<<grid, NT>>>(day, items, W1_day, W1_var, b1, W2, b2, out, G);
}

// round 16
// speedup vs baseline: 1.2258x; 1.2258x over previous
#include <cuda_runtime.h>
#include <cuda_bf16.h>
#include <cstdint>

// SplitMLP via mma.sync bf16 (hi/lo split, 3 cross-products ~ fp32 accuracy).
// cp.async pipeline: group g+1's raw fp32 inputs stream into smem while group
// g's MMA runs; convert phase does bf16 hi/lo split smem->smem. 3 CTAs/SM.
// Pitches are multiples of 16 B (cp.async alignment rule).

constexpr int B = 128;
constexpr int C = 16;
constexpr int V = 32;
constexpr int H = 64;
constexpr int O = 4;
constexpr int KTOT = 48;
constexpr int PX = 104;              // bf16 pitch: 48 hi + 48 lo + 8 pad (208 B)
constexpr int PXB = 208;
constexpr int NG = 8;                // groups per CTA
constexpr int NT = 128;              // threads

// ---- dynamic smem layout (bytes) ----
constexpr int SX   = 0;                      // bf16 X tile: 128*104*2 = 26624
constexpr int SW1  = 26624;                  // bf16 W1 tile: 64*104*2 = 13312
constexpr int SW2o = 39936;                  // fp32 W2 [o][h]: 1024
constexpr int SB1o = 40960;                  // fp32 b1: 256
constexpr int SB2o = 41216;                  // fp32 b2: 16 (+pad to 41248)
constexpr int RIT  = 41248;                  // raw items fp32, pitch 128B x128 = 16384
constexpr int RW1  = RIT + 16384;            // raw W1 fp32, pitch 192B x64 = 12288
constexpr int RW2  = RW1 + 12288;            // raw W2: 1024
constexpr int RB1  = RW2 + 1024;             // raw b1: 256
constexpr int RB2  = RB1 + 256;              // raw b2: 16
constexpr int SMEM_TOTAL = RB2 + 16;         // 71216 -> 3 CTAs/SM

typedef uint32_t u32;

// ---------- helpers ----------
__device__ __forceinline__ u32 smem_u32(const void* p) {
    u32 a;
    asm("{ .reg .u64 t; cvta.to.shared.u64 t, %1; cvt.u32.u64 %0, t; }"
        : "=r"(a) : "l"(p));
    return a;
}
__device__ __forceinline__ u32 cvt2bf16(float lo, float hi) {
    u32 d;
    asm("cvt.rn.bf16x2.f32 %0, %1, %2;" : "=r"(d) : "f"(hi), "f"(lo));
    return d;
}
__device__ __forceinline__ void ldsm4(u32* r, u32 addr) {
    asm volatile("ldmatrix.sync.aligned.m8n8.x4.shared.b16 {%0,%1,%2,%3}, [%4];"
                 : "=r"(r[0]), "=r"(r[1]), "=r"(r[2]), "=r"(r[3]) : "r"(addr));
}
__device__ __forceinline__ void mma_bf16(float* c, const u32* a, const u32* b) {
    asm volatile(
        "mma.sync.aligned.m16n8k16.row.col.f32.bf16.bf16.f32 "
        "{%0,%1,%2,%3}, {%4,%5,%6,%7}, {%8,%9}, {%0,%1,%2,%3};"
        : "+f"(c[0]), "+f"(c[1]), "+f"(c[2]), "+f"(c[3])
        : "r"(a[0]), "r"(a[1]), "r"(a[2]), "r"(a[3]), "r"(b[0]), "r"(b[1]));
}
__device__ __forceinline__ void cp16(u32 dst, const void* src) {
    asm volatile("cp.async.cg.shared.global [%0], [%1], 16;"
                 :: "r"(dst), "l"(src) : "memory");
}
__device__ __forceinline__ void cp_commit() {
    asm volatile("cp.async.commit_group;" ::: "memory");
}
__device__ __forceinline__ void cp_wait0() {
    asm volatile("cp.async.wait_group 0;" ::: "memory");
}

// Convert float4 -> bf16 hi/lo pairs and store at (row, col) + (row, col+48).
__device__ __forceinline__ void cvt_store4(__nv_bfloat16* base, int row, int col,
                                           float4 v) {
    u32 h01 = cvt2bf16(v.x, v.y);
    u32 h23 = cvt2bf16(v.z, v.w);
    float l0 = v.x - __uint_as_float(h01 << 16);
    float l1 = v.y - __uint_as_float(h01 & 0xffff0000u);
    float l2 = v.z - __uint_as_float(h23 << 16);
    float l3 = v.w - __uint_as_float(h23 & 0xffff0000u);
    u32 lo01 = cvt2bf16(l0, l1);
    u32 lo23 = cvt2bf16(l2, l3);
    *reinterpret_cast<uint2*>(base + row * PX + col) = make_uint2(h01, h23);
    *reinterpret_cast<uint2*>(base + row * PX + col + KTOT) = make_uint2(lo01, lo23);
}

// Fire-and-forget prefetch of group g's raw inputs into smem.
__device__ __forceinline__ void issue_group(
    u32 sb, int g, int t, int G,
    const float* items, const float* W1_day, const float* W1_var,
    const float* W2, const float* b1, const float* b2)
{
#pragma unroll
    for (int j = 0; j < 8; ++j) {
        int f = t + j * NT, bb = f >> 3, c = f & 7;
        cp16(sb + RIT + bb * 128 + c * 16, items + ((size_t)bb * G + g) * V + c * 4);
    }
#pragma unroll
    for (int j = 0; j < 2; ++j) {
        int f = t + j * NT, r = f >> 2, c = f & 3;
        cp16(sb + RW1 + r * 192 + c * 16, W1_day + (size_t)g * (H * C) + r * C + c * 4);
    }
#pragma unroll
    for (int j = 0; j < 4; ++j) {
        int f = t + j * NT, r = f >> 3, c = f & 7;
        cp16(sb + RW1 + r * 192 + 64 + c * 16, W1_var + (size_t)g * (H * V) + r * V + c * 4);
    }
    if (t < 64) cp16(sb + RW2 + t * 16, W2 + (size_t)g * (O * H) + t * 4);
    if (t < 16) cp16(sb + RB1 + t * 16, b1 + (size_t)g * H + t * 4);
    if (t == 0) cp16(sb + RB2, b2 + (size_t)g * O);
    cp_commit();
}

__global__ __launch_bounds__(NT, 3) void splitmlp_mma(
    const float* __restrict__ day,     // (B, C)
    const float* __restrict__ items,   // (B, G, V)
    const float* __restrict__ W1_day,  // (G, H, C)
    const float* __restrict__ W1_var,  // (G, H, V)
    const float* __restrict__ b1,      // (G, H)
    const float* __restrict__ W2,      // (G, O, H)
    const float* __restrict__ b2,      // (G, O)
    float* __restrict__ out,           // (B, G, O)
    int G)
{
    extern __shared__ char smem[];
    const u32 sb = smem_u32(smem);
    __nv_bfloat16* sX  = reinterpret_cast<__nv_bfloat16*>(smem + SX);
    __nv_bfloat16* sW1 = reinterpret_cast<__nv_bfloat16*>(smem + SW1);
    float* sW2 = reinterpret_cast<float*>(smem + SW2o);
    float* sB1 = reinterpret_cast<float*>(smem + SB1o);
    float* sB2 = reinterpret_cast<float*>(smem + SB2o);

    const int t = threadIdx.x;
    const int wid = t >> 5;
    const int lane = t & 31;
    const int g0 = blockIdx.x * NG;
    const int gEnd = (g0 + NG < G) ? (g0 + NG) : G;
    if (g0 >= G) return;

    // kick off group g0's raw prefetch immediately
    issue_group(sb, g0, t, G, items, W1_day, W1_var, W2, b1, b2);

    // day staged once per CTA: X rows, k 0..15 (+lo plane) -- group-invariant
    {
        const float4* p = reinterpret_cast<const float4*>(day);
#pragma unroll
        for (int j = 0; j < 4; ++j) {
            int f = t + j * NT;
            cvt_store4(sX, f >> 2, (f & 3) * 4, p[f]);
        }
    }

    // ---- per-lane ldmatrix addresses (group-invariant) ----
    const u32 sbX = sb + SX;
    const u32 sbW = sb + SW1;
    const int r8 = lane & 7, sel = lane >> 3;
    const int wbase = wid * 32;
    const u32 aAddr = sbX + (u32)((wbase + ((sel & 1) << 3) + r8) * PXB +
                                  ((sel & 2) ? 16 : 0));
    const u32 bAddr = sbW + (u32)(((((sel >> 1) & 1) << 3) + r8) * PXB +
                                  ((sel & 1) << 4));
    constexpr int MT_STRIDE = 16 * PXB;
    constexpr int NT_STRIDE = 16 * PXB;
    constexpr int LO_OFF = KTOT * 2;
    const int q = lane & 3;

#pragma unroll 1
    for (int g = g0; g < gEnd; ++g) {
        // raw g ready (this thread) + all threads done reading tiles of g-1
        cp_wait0();
        __syncthreads();

        // ---- convert raw fp32 -> bf16 hi/lo tiles ----
#pragma unroll
        for (int j = 0; j < 8; ++j) {
            int f = t + j * NT, r = f >> 3, c = f & 7;
            float4 v = *reinterpret_cast<const float4*>(smem + RIT + r * 128 + c * 16);
            cvt_store4(sX, r, 16 + c * 4, v);
        }
#pragma unroll
        for (int j = 0; j < 2; ++j) {
            int f = t + j * NT, r = f >> 2, c = f & 3;
            float4 v = *reinterpret_cast<const float4*>(smem + RW1 + r * 192 + c * 16);
            cvt_store4(sW1, r, c * 4, v);
        }
#pragma unroll
        for (int j = 0; j < 4; ++j) {
            int f = t + j * NT, r = f >> 3, c = f & 7;
            float4 v = *reinterpret_cast<const float4*>(smem + RW1 + r * 192 + 64 + c * 16);
            cvt_store4(sW1, r, 16 + c * 4, v);
        }
        if (t < 64)
            *reinterpret_cast<float4*>(smem + SW2o + t * 16) =
                *reinterpret_cast<const float4*>(smem + RW2 + t * 16);
        if (t < 16)
            *reinterpret_cast<float4*>(smem + SB1o + t * 16) =
                *reinterpret_cast<const float4*>(smem + RB1 + t * 16);
        if (t == 0)
            *reinterpret_cast<float4*>(smem + SB2o) =
                *reinterpret_cast<const float4*>(smem + RB2);
        __syncthreads();   // tiles ready; raw buffer free for next prefetch

        // ---- prefetch next group's raw data (overlaps MMA below) ----
        if (g + 1 < gEnd)
            issue_group(sb, g + 1, t, G, items, W1_day, W1_var, W2, b1, b2);

        // ---- fc1 MMA: 3 k-chunks x 3 hi/lo passes ----
        float acc[2][8][4];
#pragma unroll
        for (int mt = 0; mt < 2; ++mt)
#pragma unroll
            for (int nt = 0; nt < 8; ++nt)
#pragma unroll
                for (int i = 0; i < 4; ++i) acc[mt][nt][i] = 0.0f;

#pragma unroll
        for (int kk = 0; kk < 3; ++kk) {
            const int kOff = kk * 32;
            u32 ah[2][4], bh[4][4];
#pragma unroll
            for (int mt = 0; mt < 2; ++mt)
                ldsm4(ah[mt], aAddr + mt * MT_STRIDE + kOff);
#pragma unroll
            for (int np = 0; np < 4; ++np)
                ldsm4(bh[np], bAddr + np * NT_STRIDE + kOff);
            // Ah * Bh
#pragma unroll
            for (int mt = 0; mt < 2; ++mt)
#pragma unroll
                for (int np = 0; np < 4; ++np) {
                    mma_bf16(acc[mt][2 * np + 0], ah[mt], &bh[np][0]);
                    mma_bf16(acc[mt][2 * np + 1], ah[mt], &bh[np][2]);
                }
            // Ah * Bl
#pragma unroll
            for (int np = 0; np < 4; ++np) {
                u32 bl[4];
                ldsm4(bl, bAddr + np * NT_STRIDE + LO_OFF + kOff);
#pragma unroll
                for (int mt = 0; mt < 2; ++mt) {
                    mma_bf16(acc[mt][2 * np + 0], ah[mt], &bl[0]);
                    mma_bf16(acc[mt][2 * np + 1], ah[mt], &bl[2]);
                }
            }
            // Al * Bh
#pragma unroll
            for (int mt = 0; mt < 2; ++mt) {
                u32 al[4];
                ldsm4(al, aAddr + mt * MT_STRIDE + LO_OFF + kOff);
#pragma unroll
                for (int np = 0; np < 4; ++np) {
                    mma_bf16(acc[mt][2 * np + 0], al, &bh[np][0]);
                    mma_bf16(acc[mt][2 * np + 1], al, &bh[np][2]);
                }
            }
        }

        // ---- epilogue: relu(h + b1), fc2, quad reduction ----
        float y[2][2][4];
#pragma unroll
        for (int mt = 0; mt < 2; ++mt)
#pragma unroll
            for (int rp = 0; rp < 2; ++rp)
#pragma unroll
                for (int o = 0; o < O; ++o) y[mt][rp][o] = 0.0f;

#pragma unroll
        for (int nt = 0; nt < 8; ++nt) {
            const int h0 = nt * 8 + q * 2;
            const float2 bb = *reinterpret_cast<const float2*>(&sB1[h0]);
#pragma unroll
            for (int mt = 0; mt < 2; ++mt) {
                float v00 = fmaxf(acc[mt][nt][0] + bb.x, 0.0f);
                float v01 = fmaxf(acc[mt][nt][1] + bb.y, 0.0f);
                float v10 = fmaxf(acc[mt][nt][2] + bb.x, 0.0f);
                float v11 = fmaxf(acc[mt][nt][3] + bb.y, 0.0f);
#pragma unroll
                for (int o = 0; o < O; ++o) {
                    const float2 w = *reinterpret_cast<const float2*>(&sW2[o * H + h0]);
                    y[mt][0][o] = fmaf(v00, w.x, fmaf(v01, w.y, y[mt][0][o]));
                    y[mt][1][o] = fmaf(v10, w.x, fmaf(v11, w.y, y[mt][1][o]));
                }
            }
        }
#pragma unroll
        for (int d = 1; d < 4; d <<= 1) {
#pragma unroll
            for (int mt = 0; mt < 2; ++mt)
#pragma unroll
                for (int rp = 0; rp < 2; ++rp)
#pragma unroll
                    for (int o = 0; o < O; ++o)
                        y[mt][rp][o] += __shfl_xor_sync(0xffffffffu, y[mt][rp][o], d);
        }

        if (q == 0) {
            const int rbase = wbase + (lane >> 2);
#pragma unroll
            for (int mt = 0; mt < 2; ++mt)
#pragma unroll
                for (int rp = 0; rp < 2; ++rp) {
                    const int row = rbase + mt * 16 + rp * 8;
                    float4 res = make_float4(y[mt][rp][0] + sB2[0],
                                             y[mt][rp][1] + sB2[1],
                                             y[mt][rp][2] + sB2[2],
                                             y[mt][rp][3] + sB2[3]);
                    *reinterpret_cast<float4*>(out + ((size_t)row * G + g) * O) = res;
                }
        }
        // no trailing barrier: next iteration's top barrier covers the hazard
    }
}

extern "C" void kernel_launch(void* const* d_in, const int* in_sizes, int n_in,
                              void* d_out, int out_size) {
    const float* day    = (const float*)d_in[0];
    const float* items  = (const float*)d_in[1];
    const float* W1_day = (const float*)d_in[2];
    const float* W1_var = (const float*)d_in[3];
    const float* b1     = (const float*)d_in[4];
    const float* W2     = (const float*)d_in[5];
    const float* b2     = (const float*)d_in[6];
    float* out = (float*)d_out;

    const int G = in_sizes[1] / (B * V);   // items = B*G*V
    const int grid = (G + NG - 1) / NG;

    cudaFuncSetAttribute(splitmlp_mma,
                         cudaFuncAttributeMaxDynamicSharedMemorySize, SMEM_TOTAL);
    splitmlp_mma<<<grid, NT, SMEM_TOTAL>>>(day, items, W1_day, W1_var, b1, W2,
                                           b2, out, G);
}